// round 16
// baseline (speedup 1.0000x reference)
#include <cuda_runtime.h>
#include <cuda_fp16.h>
#include <math.h>
#include <stdint.h>

// ---------------- Problem dims ----------------
#define B_      8
#define LQ_     512
#define LK_     256
#define DM_     512
#define DI_     1024
#define DS_     16
#define DTR_    32
#define NBLK_   4
#define NHEAD_  4
#define DH_     128
#define NOUT_   6

#define ROWS_Q  (B_*LQ_)   // 4096
#define ROWS_K  (B_*LK_)   // 2048
#define KVS_    1024       // combined K|V row stride

// ---------------- Scratch (static device globals; no allocation) ----------------
__device__ float g_x   [ROWS_Q * DM_];
__device__ float g_h   [ROWS_Q * DM_];
__device__ float g_xz  [ROWS_Q * 2 * DI_];
__device__ float g_xc  [ROWS_Q * DI_];
__device__ float g_dbl [ROWS_Q * 64];
__device__ float g_dlt [ROWS_Q * DI_];
__device__ float g_q   [ROWS_Q * DM_];
__device__ float g_kv  [ROWS_K * KVS_];
__device__ float g_bkv [KVS_];
__device__ __align__(16) __half g_A6   [ROWS_Q * 3 * 1024];   // activation splits (2 halves of 4096x1536)
__device__ __align__(16) __half g_Aag  [ROWS_K * 3 * 512];    // agent split (constant input)
__device__ __align__(16) __half g_B6all[25600000];            // all weight splits (~48.4MB used)

// ---------------- fp16 split helpers ----------------
__device__ __forceinline__ uint32_t pack2h(__half a, __half b) {
    return (uint32_t)__half_as_ushort(a) | ((uint32_t)__half_as_ushort(b) << 16);
}
__device__ __forceinline__ void split2(float a, __half& h, __half& m) {
    h = __float2half(a);
    m = __float2half(a - __half2float(h));
}
// pack a pair of A-elements into 3 u32: halves [h0,m0,h0,h1,m1,h1]
__device__ __forceinline__ void packA_pair(float a0, float a1, uint32_t* dst) {
    __half h0, m0, h1, m1;
    split2(a0, h0, m0); split2(a1, h1, m1);
    dst[0] = pack2h(h0, m0);
    dst[1] = pack2h(h0, h1);
    dst[2] = pack2h(m1, h1);
}
__device__ __forceinline__ uint32_t smem_u32(const void* p) {
    uint32_t a;
    asm("{ .reg .u64 t; cvta.to.shared.u64 t, %1; cvt.u32.u64 %0, t; }" : "=r"(a) : "l"(p));
    return a;
}

// ---------------- mma.sync m16n8k16 f16->f32 ----------------
__device__ __forceinline__ void mma16816(float* c, const uint32_t* a, const uint32_t* b) {
    asm volatile("mma.sync.aligned.m16n8k16.row.col.f32.f16.f16.f32 "
        "{%0,%1,%2,%3}, {%4,%5,%6,%7}, {%8,%9}, {%0,%1,%2,%3};"
        : "+f"(c[0]), "+f"(c[1]), "+f"(c[2]), "+f"(c[3])
        : "r"(a[0]), "r"(a[1]), "r"(a[2]), "r"(a[3]), "r"(b[0]), "r"(b[1]));
}

// ================= Pipelined HMMA GEMM (256 threads, 8 warps 2x4) =================
// C[M,N] = A6[M,Keff] * B6[N,Keff]^T.  Keff % 64 == 0.
// SPLITOUT: write 3-split halves to C (as A6 [M,3*ldc]) instead of fp32.
template<int BM, int BN, bool ACCUM, bool SPLITOUT>
__global__ void __launch_bounds__(256)
mma_gemm_pipe(const __half* __restrict__ A6, const __half* __restrict__ B6,
              const float* __restrict__ bias, float* __restrict__ C, int ldc, int Keff)
{
    constexpr int STAGES = 3;
    constexpr int WM = BM / 2, WN = BN / 4;
    constexpr int MT = WM / 16, NT = WN / 8;
    constexpr int STAGE_BYTES = (BM + BN) * 128;
    extern __shared__ __align__(16) char smem[];
    const uint32_t sbase = smem_u32(smem);

    const int tid = threadIdx.x, lane = tid & 31, w = tid >> 5;
    const int wm0 = (w >> 2) * WM, wn0 = (w & 3) * WN;
    const int bm = blockIdx.y * BM, bn = blockIdx.x * BN;

    const int ktiles = Keff >> 6;

    auto load_stage = [&](int s, int kt) {
        if (kt >= ktiles) {
            asm volatile("cp.async.commit_group;" ::: "memory");
            return;
        }
        const uint32_t aST = sbase + s * STAGE_BYTES;
        const uint32_t bST = aST + BM * 128;
        const size_t gk = ((size_t)kt) << 6;
        #pragma unroll
        for (int r = 0; r < BM * 8 / 256; r++) {
            int idx = tid + r * 256;
            int row = idx >> 3, cc = idx & 7;
            uint32_t d = aST + row * 128 + ((cc ^ (row & 7)) << 4);
            const __half* g = A6 + (size_t)(bm + row) * Keff + gk + cc * 8;
            asm volatile("cp.async.cg.shared.global [%0], [%1], 16;" :: "r"(d), "l"(g));
        }
        #pragma unroll
        for (int r = 0; r < BN * 8 / 256; r++) {
            int idx = tid + r * 256;
            int row = idx >> 3, cc = idx & 7;
            uint32_t d = bST + row * 128 + ((cc ^ (row & 7)) << 4);
            const __half* g = B6 + (size_t)(bn + row) * Keff + gk + cc * 8;
            asm volatile("cp.async.cg.shared.global [%0], [%1], 16;" :: "r"(d), "l"(g));
        }
        asm volatile("cp.async.commit_group;" ::: "memory");
    };

    float acc[MT][NT][4];
    #pragma unroll
    for (int i = 0; i < MT; i++)
        #pragma unroll
        for (int j = 0; j < NT; j++)
            #pragma unroll
            for (int q = 0; q < 4; q++) acc[i][j][q] = 0.f;

    #pragma unroll
    for (int s = 0; s < STAGES - 1; s++) load_stage(s, s);

    uint32_t af[2][MT][4], bf[2][NT][2];

    for (int kt = 0; kt < ktiles; kt++) {
        asm volatile("cp.async.wait_group %0;" :: "n"(STAGES - 2) : "memory");
        __syncthreads();
        load_stage((kt + 2) % STAGES, kt + 2);

        const int s = kt % STAGES;
        const uint32_t aST = sbase + s * STAGE_BYTES;
        const uint32_t bST = aST + BM * 128;

        auto load_frags = [&](int buf, int g) {
            const int kk = g * 16;
            #pragma unroll
            for (int i = 0; i < MT; i++) {
                int row = wm0 + i * 16 + (lane & 15);
                int cb = (kk >> 3) + (lane >> 4);
                uint32_t ad = aST + row * 128 + (((cb ^ (row & 7))) << 4);
                asm volatile("ldmatrix.sync.aligned.m8n8.x4.shared.b16 {%0,%1,%2,%3}, [%4];"
                    : "=r"(af[buf][i][0]), "=r"(af[buf][i][1]),
                      "=r"(af[buf][i][2]), "=r"(af[buf][i][3]) : "r"(ad));
            }
            #pragma unroll
            for (int j = 0; j < NT; j++) {
                int row = wn0 + j * 8 + (lane & 7);
                int cb = (kk >> 3) + ((lane >> 3) & 1);
                uint32_t bd = bST + row * 128 + (((cb ^ (row & 7))) << 4);
                asm volatile("ldmatrix.sync.aligned.m8n8.x2.shared.b16 {%0,%1}, [%2];"
                    : "=r"(bf[buf][j][0]), "=r"(bf[buf][j][1]) : "r"(bd));
            }
        };

        load_frags(0, 0);
        #pragma unroll
        for (int g = 0; g < 4; g++) {
            if (g < 3) load_frags((g + 1) & 1, g + 1);
            const int buf = g & 1;
            #pragma unroll
            for (int j = 0; j < NT; j++)
                #pragma unroll
                for (int i = 0; i < MT; i++) mma16816(acc[i][j], af[buf][i], bf[buf][j]);
        }
    }
    asm volatile("cp.async.wait_group 0;" ::: "memory");

    const int g = lane >> 2, tg = lane & 3;
    #pragma unroll
    for (int i = 0; i < MT; i++) {
        #pragma unroll
        for (int j = 0; j < NT; j++) {
            int cn = bn + wn0 + j * 8 + tg * 2;
            #pragma unroll
            for (int hh = 0; hh < 2; hh++) {
                int rm = bm + wm0 + i * 16 + g + hh * 8;
                float v0 = acc[i][j][hh * 2 + 0], v1 = acc[i][j][hh * 2 + 1];
                if (bias) { v0 += bias[cn]; v1 += bias[cn + 1]; }
                if (SPLITOUT) {
                    __half* A6o = reinterpret_cast<__half*>(C);
                    packA_pair(v0, v1, reinterpret_cast<uint32_t*>(
                        A6o + (size_t)rm * (3 * ldc) + 3 * cn));
                } else {
                    size_t o = (size_t)rm * ldc + cn;
                    if (ACCUM) { v0 += C[o]; v1 += C[o + 1]; }
                    *reinterpret_cast<float2*>(&C[o]) = make_float2(v0, v1);
                }
            }
        }
    }
}

// ================= dt_proj GEMM: fp32 A (pdbl), inline split, Keff=96 =================
// C[4096,1024] = softplus(split3(pdbl[:, :32]) @ B6dt^T + dtb). BM=BN=128.
#define ASK_ 104
__global__ void __launch_bounds__(256)
dt_gemm(const float* __restrict__ Apdbl, const __half* __restrict__ B6,
        const float* __restrict__ bias, float* __restrict__ C)
{
    extern __shared__ __align__(16) char smem[];
    __half* As = reinterpret_cast<__half*>(smem);               // [128][104]
    __half* Bs = reinterpret_cast<__half*>(smem) + 128 * ASK_;  // [128][104]

    const int tid = threadIdx.x;
    const int lane = tid & 31, w = tid >> 5;
    const int wm0 = (w >> 2) * 64, wn0 = (w & 3) * 32;  // 2x4 warps, WM=64, WN=32
    const int bm = blockIdx.y * 128, bn = blockIdx.x * 128;
    const int g = lane >> 2, tg = lane & 3;

    #pragma unroll
    for (int r = 0; r < 8; r++) {
        int idx = tid + r * 256;
        int row = idx >> 4, pr = idx & 15;
        float2 a = *reinterpret_cast<const float2*>(Apdbl + (size_t)(bm + row) * 64 + pr * 2);
        packA_pair(a.x, a.y, reinterpret_cast<uint32_t*>(&As[row * ASK_ + pr * 6]));
    }
    #pragma unroll
    for (int r = 0; r < 6; r++) {
        int idx = tid + r * 256;
        int row = idx / 12, c = idx % 12;
        *reinterpret_cast<uint4*>(&Bs[row * ASK_ + c * 8]) =
            *reinterpret_cast<const uint4*>(B6 + (size_t)(bn + row) * 96 + c * 8);
    }
    __syncthreads();

    float acc[4][4][4];
    #pragma unroll
    for (int i = 0; i < 4; i++)
        #pragma unroll
        for (int j = 0; j < 4; j++)
            #pragma unroll
            for (int q = 0; q < 4; q++) acc[i][j][q] = 0.f;

    #pragma unroll
    for (int kk = 0; kk < 96; kk += 16) {
        uint32_t af[4][4];
        #pragma unroll
        for (int i = 0; i < 4; i++) {
            const __half* base = &As[(wm0 + i * 16 + g) * ASK_ + kk + tg * 2];
            af[i][0] = *reinterpret_cast<const uint32_t*>(base);
            af[i][1] = *reinterpret_cast<const uint32_t*>(base + 8 * ASK_);
            af[i][2] = *reinterpret_cast<const uint32_t*>(base + 8);
            af[i][3] = *reinterpret_cast<const uint32_t*>(base + 8 * ASK_ + 8);
        }
        #pragma unroll
        for (int j = 0; j < 4; j++) {
            const __half* bb = &Bs[(wn0 + j * 8 + g) * ASK_ + kk + tg * 2];
            uint32_t bfr[2] = { *reinterpret_cast<const uint32_t*>(bb),
                                *reinterpret_cast<const uint32_t*>(bb + 8) };
            #pragma unroll
            for (int i = 0; i < 4; i++) mma16816(acc[i][j], af[i], bfr);
        }
    }

    #pragma unroll
    for (int i = 0; i < 4; i++) {
        #pragma unroll
        for (int j = 0; j < 4; j++) {
            int cn = bn + wn0 + j * 8 + tg * 2;
            #pragma unroll
            for (int hh = 0; hh < 2; hh++) {
                int rm = bm + wm0 + i * 16 + g + hh * 8;
                float v0 = acc[i][j][hh * 2 + 0] + bias[cn];
                float v1 = acc[i][j][hh * 2 + 1] + bias[cn + 1];
                v0 = (v0 > 20.f) ? v0 : log1pf(__expf(v0));
                v1 = (v1 > 20.f) ? v1 : log1pf(__expf(v1));
                *reinterpret_cast<float2*>(&C[(size_t)rm * DI_ + cn]) = make_float2(v0, v1);
            }
        }
    }
}

// ================= Mega weight-split prepass (+ KV bias concat) =================
#define NWD 22
struct SplitDescs {
    const float* W[NWD];
    __half*      dst[NWD];
    int K[NWD];
    int N[NWD];
    int tileBase[NWD];
    const float* bk;
    const float* bv;
    float*       bkv;
};
__global__ void splitB_all(SplitDescs da)
{
    int t = blockIdx.x;
    int tx = threadIdx.x, ty = threadIdx.y;   // (32,8)
    if (t == 0) {
        int flat = ty * 32 + tx;
        for (int j = flat; j < KVS_; j += 256)
            da.bkv[j] = (j < 512) ? da.bk[j] : da.bv[j - 512];
    }
    int di = 0;
    #pragma unroll
    for (int i = 1; i < NWD; i++) if (t >= da.tileBase[i]) di = i;
    const float* W = da.W[di];
    __half* dst = da.dst[di];
    int K = da.K[di], N = da.N[di];
    int local = t - da.tileBase[di];
    int tilesN = N >> 5;
    int tk = local / tilesN, tn = local - tk * tilesN;
    int n0 = tn * 32, k0 = tk * 32;

    __shared__ float s[32][33];
    #pragma unroll
    for (int j = 0; j < 32; j += 8)
        s[ty + j][tx] = W[(size_t)(k0 + ty + j) * N + n0 + tx];
    __syncthreads();
    int Keff = 3 * K;
    #pragma unroll
    for (int j = 0; j < 32; j += 8) {
        int n = n0 + ty + j, k = k0 + tx;
        __half h, m; split2(s[tx][ty + j], h, m);
        __half* d = dst + (size_t)n * Keff + 3 * (size_t)k;
        d[0] = h; d[1] = h; d[2] = m;
    }
}

// ================= Activation split (row-major) =================
__global__ void splitA_kernel(const float* __restrict__ A, int lda, int k2shift, int total,
                              __half* __restrict__ A6)
{
    int idx = blockIdx.x * blockDim.x + threadIdx.x;
    if (idx >= total) return;
    int K2 = 1 << k2shift;
    int m = idx >> k2shift, kp = idx & (K2 - 1);
    float2 a = *reinterpret_cast<const float2*>(A + (size_t)m * lda + kp * 2);
    packA_pair(a.x, a.y, reinterpret_cast<uint32_t*>(A6 + (size_t)m * (6 * (size_t)K2) + kp * 6));
}

// ---------------- RMSNorm fused with A split (D=512) ----------------
__global__ void rmsnorm_split_kernel(const float* __restrict__ X,
                                     const float* __restrict__ w,
                                     __half* __restrict__ A6)
{
    int row = blockIdx.x;
    const float* x = X + (size_t)row * DM_;
    float s = 0.f;
    for (int j = threadIdx.x; j < DM_; j += 128) { float v = x[j]; s += v * v; }
    #pragma unroll
    for (int o = 16; o; o >>= 1) s += __shfl_xor_sync(0xffffffffu, s, o);
    __shared__ float ws[4];
    if ((threadIdx.x & 31) == 0) ws[threadIdx.x >> 5] = s;
    __syncthreads();
    float rs = rsqrtf((ws[0] + ws[1] + ws[2] + ws[3]) / (float)DM_ + 1e-5f);
    __half* dst = A6 + (size_t)row * (3 * DM_);
    for (int p = threadIdx.x; p < DM_ / 2; p += 128) {
        int k = p * 2;
        packA_pair(x[k] * rs * w[k], x[k + 1] * rs * w[k + 1],
                   reinterpret_cast<uint32_t*>(dst + p * 6));
    }
}

// ---------------- Depthwise conv (K=4) + SiLU, fused with A split ----------------
__global__ void conv_silu_split_kernel(const float* __restrict__ xz,
                                       const float* __restrict__ cw,
                                       const float* __restrict__ cb,
                                       float* __restrict__ xc,
                                       __half* __restrict__ A6)
{
    int idx = blockIdx.x * blockDim.x + threadIdx.x;
    if (idx >= B_ * LQ_ * (DI_ / 2)) return;
    int d2 = idx & 511;
    int l  = (idx >> 9) & 511;
    int b  = idx >> 18;
    int d  = d2 * 2;
    const float* base = xz + (size_t)b * LQ_ * 2 * DI_ + d;
    float s0 = cb[d], s1 = cb[d + 1];
    #pragma unroll
    for (int k = 0; k < 4; k++) {
        int ll = l - 3 + k;
        if (ll >= 0) {
            float2 v = *reinterpret_cast<const float2*>(base + (size_t)ll * (2 * DI_));
            s0 = fmaf(cw[d * 4 + k], v.x, s0);
            s1 = fmaf(cw[(d + 1) * 4 + k], v.y, s1);
        }
    }
    float y0 = s0 / (1.f + __expf(-s0));
    float y1 = s1 / (1.f + __expf(-s1));
    int row = b * LQ_ + l;
    *reinterpret_cast<float2*>(xc + (size_t)row * DI_ + d) = make_float2(y0, y1);
    packA_pair(y0, y1, reinterpret_cast<uint32_t*>(A6 + (size_t)row * (3 * DI_) + d2 * 6));
}

// ---------------- Selective scan: 4 threads per (b,d), fused with ys split ----------------
__global__ void scan_kernel(const float* __restrict__ delta,
                            const float* __restrict__ xc,
                            const float* __restrict__ dbl,
                            const float* __restrict__ xz,
                            const float* __restrict__ A_log,
                            const float* __restrict__ Dskip,
                            __half* __restrict__ A6)
{
    int t = blockIdx.x * blockDim.x + threadIdx.x;   // 32768 threads
    int ch = t >> 2, sub = t & 3;
    int d = ch & (DI_ - 1);
    int b = ch >> 10;
    int n0 = sub * 4;

    float A[4], h[4];
    #pragma unroll
    for (int j = 0; j < 4; j++) { A[j] = -__expf(A_log[d * DS_ + n0 + j]); h[j] = 0.f; }
    float Dv = Dskip[d];
    bool writer = ((t & 7) == 0);
    int d2 = d >> 1;

    for (int l = 0; l < LQ_; l++) {
        int row = b * LQ_ + l;
        float dt = delta[(size_t)row * DI_ + d];
        float u  = xc[(size_t)row * DI_ + d];
        float du = dt * u;
        float4 Bv = *reinterpret_cast<const float4*>(dbl + (size_t)row * 64 + DTR_ + n0);
        float4 Cv = *reinterpret_cast<const float4*>(dbl + (size_t)row * 64 + DTR_ + DS_ + n0);
        float y;
        {
            float dA0 = __expf(dt * A[0]); h[0] = fmaf(dA0, h[0], du * Bv.x);
            float dA1 = __expf(dt * A[1]); h[1] = fmaf(dA1, h[1], du * Bv.y);
            float dA2 = __expf(dt * A[2]); h[2] = fmaf(dA2, h[2], du * Bv.z);
            float dA3 = __expf(dt * A[3]); h[3] = fmaf(dA3, h[3], du * Bv.w);
            y = h[0] * Cv.x + h[1] * Cv.y + h[2] * Cv.z + h[3] * Cv.w;
        }
        y += __shfl_xor_sync(0xffffffffu, y, 1);
        y += __shfl_xor_sync(0xffffffffu, y, 2);
        float z = xz[(size_t)row * (2 * DI_) + DI_ + d];
        float sz = z / (1.f + __expf(-z));
        float yv = (y + u * Dv) * sz;
        float yo = __shfl_xor_sync(0xffffffffu, yv, 4);
        if (writer) {
            packA_pair(yv, yo,
                reinterpret_cast<uint32_t*>(A6 + (size_t)row * (3 * DI_) + d2 * 6));
        }
    }
}

// ---------------- Attention (fp32 SIMT), writes 3-split A6 directly ----------------
__global__ void attn_kernel(const float* __restrict__ Q,
                            const float* __restrict__ KV,
                            __half* __restrict__ A6)
{
    const int qt = blockIdx.x * 16;
    const int h  = blockIdx.y;
    const int b  = blockIdx.z;
    __shared__ float Qs[16][128];
    __shared__ float Ks[32][128];
    __shared__ float S[16][256];
    const int tid = threadIdx.x;
    const float* Kb = KV;
    const float* Vb = KV + 512;

    #pragma unroll
    for (int j = 0; j < 8; j++) {
        int idx = tid + j * 256;
        int qi = idx >> 7, dd = idx & 127;
        Qs[qi][dd] = Q[((size_t)(b * LQ_ + qt + qi)) * DM_ + h * DH_ + dd];
    }
    const float scale = 0.08838834764831845f;
    for (int kc = 0; kc < 8; kc++) {
        #pragma unroll
        for (int j = 0; j < 16; j++) {
            int idx = tid + j * 256;
            int ki = idx >> 7, dd = idx & 127;
            Ks[ki][dd] = Kb[((size_t)(b * LK_ + kc * 32 + ki)) * KVS_ + h * DH_ + dd];
        }
        __syncthreads();
        #pragma unroll
        for (int j = 0; j < 2; j++) {
            int p = tid + j * 256;
            int qi = p >> 5, ki = p & 31;
            float s = 0.f;
            #pragma unroll 4
            for (int dd = 0; dd < 128; dd++) s = fmaf(Qs[qi][dd], Ks[ki][dd], s);
            S[qi][kc * 32 + ki] = s * scale;
        }
        __syncthreads();
    }
    {
        int warp = tid >> 5, lane = tid & 31;
        for (int r = warp * 2; r < warp * 2 + 2; r++) {
            float m = -1e30f;
            #pragma unroll
            for (int j = lane; j < 256; j += 32) m = fmaxf(m, S[r][j]);
            #pragma unroll
            for (int o = 16; o; o >>= 1) m = fmaxf(m, __shfl_xor_sync(0xffffffffu, m, o));
            float sum = 0.f;
            #pragma unroll
            for (int j = lane; j < 256; j += 32) {
                float e = __expf(S[r][j] - m);
                S[r][j] = e; sum += e;
            }
            #pragma unroll
            for (int o = 16; o; o >>= 1) sum += __shfl_xor_sync(0xffffffffu, sum, o);
            float inv = 1.f / sum;
            #pragma unroll
            for (int j = lane; j < 256; j += 32) S[r][j] *= inv;
        }
    }
    __syncthreads();
    {
        int dd = tid & 127, qg = tid >> 7;
        float acc[8];
        #pragma unroll
        for (int r = 0; r < 8; r++) acc[r] = 0.f;
        for (int k = 0; k < 256; k++) {
            float v = Vb[((size_t)(b * LK_ + k)) * KVS_ + h * DH_ + dd];
            #pragma unroll
            for (int r = 0; r < 8; r++) acc[r] = fmaf(S[qg * 8 + r][k], v, acc[r]);
        }
        int c = h * DH_ + dd;
        int pbase = 3 * (c & ~1);
        #pragma unroll
        for (int r = 0; r < 8; r++) {
            int qi = qg * 8 + r;
            __half* dst = A6 + (size_t)(b * LQ_ + qt + qi) * (3 * DM_) + pbase;
            __half hh, mm; split2(acc[r], hh, mm);
            if (c & 1) { dst[3] = hh; dst[4] = mm; dst[5] = hh; }
            else       { dst[0] = hh; dst[1] = mm; dst[2] = hh; }
        }
    }
}

// ---------------- N=6 head GEMM + fused argmax ----------------
__global__ void head_gemm_kernel(const float* __restrict__ A,
                                 const float* __restrict__ W,
                                 const float* __restrict__ bias,
                                 float* __restrict__ C,
                                 float* __restrict__ preds, int writePreds,
                                 int M, int N, int K)
{
    __shared__ __align__(16) float As[16][64];
    __shared__ float Ws[16][8];
    const int bm = blockIdx.y * 64;
    const int tid = threadIdx.x;
    const int tx = tid & 15, ty = tid >> 4;
    float acc[4] = {0.f, 0.f, 0.f, 0.f};
    for (int k0 = 0; k0 < K; k0 += 16) {
        #pragma unroll
        for (int j = 0; j < 4; j++) {
            int idx = tid + j * 256;
            int m = idx >> 4, k = idx & 15;
            As[k][m] = A[(size_t)(bm + m) * K + (k0 + k)];
        }
        if (tid < 16 * 8) {
            int k = tid >> 3, n = tid & 7;
            Ws[k][n] = (n < N) ? W[(size_t)(k0 + k) * N + n] : 0.f;
        }
        __syncthreads();
        if (tx < 8) {
            #pragma unroll
            for (int k = 0; k < 16; k++) {
                float wv = Ws[k][tx];
                #pragma unroll
                for (int r = 0; r < 4; r++) acc[r] = fmaf(As[k][ty * 4 + r], wv, acc[r]);
            }
        }
        __syncthreads();
    }
    #pragma unroll
    for (int r = 0; r < 4; r++) {
        int row = bm + ty * 4 + r;
        float v = (tx < N) ? (acc[r] + bias[tx]) : -3.4e38f;
        if (tx < N) C[(size_t)row * N + tx] = v;
        if (writePreds) {
            float bv2 = v;
            int bi = tx;
            #pragma unroll
            for (int o = 8; o; o >>= 1) {
                float ov = __shfl_xor_sync(0xffffffffu, bv2, o);
                int oi = __shfl_xor_sync(0xffffffffu, bi, o);
                if (ov > bv2 || (ov == bv2 && oi < bi)) { bv2 = ov; bi = oi; }
            }
            if (tx == 0) preds[row] = (float)bi;
        }
    }
}

// ---------------- Host launch ----------------
#define SMEM_PIPE_128 (3 * (128 + 128) * 128)   // 98304
#define SMEM_PIPE_64M (3 * (64 + 128) * 128)    // 73728 (64x128)
#define SMEM_PIPE_64S (3 * (64 + 64) * 128)     // 49152 (64x64)
#define SMEM_DT       (2 * 128 * ASK_ * 2)      // 53248

extern "C" void kernel_launch(void* const* d_in, const int* in_sizes, int n_in,
                              void* d_out, int out_size)
{
    const float* agent   = (const float*)d_in[0];
    const float* lane    = (const float*)d_in[1];
    const float* lane_W  = (const float*)d_in[2];
    const float* lane_b  = (const float*)d_in[3];
    const float* norm_w  = (const float*)d_in[4];
    const float* inpW    = (const float*)d_in[5];
    const float* convw   = (const float*)d_in[6];
    const float* convb   = (const float*)d_in[7];
    const float* xprW    = (const float*)d_in[8];
    const float* dtW     = (const float*)d_in[9];
    const float* dtb     = (const float*)d_in[10];
    const float* A_log   = (const float*)d_in[11];
    const float* Dskip   = (const float*)d_in[12];
    const float* outW    = (const float*)d_in[13];
    const float* fnw     = (const float*)d_in[14];
    const float* Wq      = (const float*)d_in[15];
    const float* Wk      = (const float*)d_in[16];
    const float* Wv      = (const float*)d_in[17];
    const float* Wo      = (const float*)d_in[18];
    const float* bq      = (const float*)d_in[19];
    const float* bk      = (const float*)d_in[20];
    const float* bv      = (const float*)d_in[21];
    const float* bo      = (const float*)d_in[22];
    const float* linW    = (const float*)d_in[23];
    const float* linb    = (const float*)d_in[24];
    const float* loutW   = (const float*)d_in[25];
    const float* loutb   = (const float*)d_in[26];

    float *px, *ph, *pxz, *pxc, *pdbl, *pdlt, *pq, *pkv, *pbkv;
    __half *pA6, *pAag, *pB;
    cudaGetSymbolAddress((void**)&px,   g_x);
    cudaGetSymbolAddress((void**)&ph,   g_h);
    cudaGetSymbolAddress((void**)&pxz,  g_xz);
    cudaGetSymbolAddress((void**)&pxc,  g_xc);
    cudaGetSymbolAddress((void**)&pdbl, g_dbl);
    cudaGetSymbolAddress((void**)&pdlt, g_dlt);
    cudaGetSymbolAddress((void**)&pq,   g_q);
    cudaGetSymbolAddress((void**)&pkv,  g_kv);
    cudaGetSymbolAddress((void**)&pbkv, g_bkv);
    cudaGetSymbolAddress((void**)&pA6,  g_A6);
    cudaGetSymbolAddress((void**)&pAag, g_Aag);
    cudaGetSymbolAddress((void**)&pB,   g_B6all);
    __half* pA6b = pA6 + (size_t)ROWS_Q * 1536;   // disjoint second half of g_A6

    cudaFuncSetAttribute(mma_gemm_pipe<128,128,false,false>,
                         cudaFuncAttributeMaxDynamicSharedMemorySize, SMEM_PIPE_128);
    cudaFuncSetAttribute(mma_gemm_pipe<64,128,false,false>,
                         cudaFuncAttributeMaxDynamicSharedMemorySize, SMEM_PIPE_64M);
    cudaFuncSetAttribute(mma_gemm_pipe<64,128,true,false>,
                         cudaFuncAttributeMaxDynamicSharedMemorySize, SMEM_PIPE_64M);
    cudaFuncSetAttribute(mma_gemm_pipe<64,128,false,true>,
                         cudaFuncAttributeMaxDynamicSharedMemorySize, SMEM_PIPE_64M);
    cudaFuncSetAttribute(mma_gemm_pipe<64,64,false,false>,
                         cudaFuncAttributeMaxDynamicSharedMemorySize, SMEM_PIPE_64S);
    cudaFuncSetAttribute(dt_gemm,
                         cudaFuncAttributeMaxDynamicSharedMemorySize, SMEM_DT);

    float* probs = (float*)d_out;

    // ---- build weight-split descriptor table ----
    SplitDescs da;
    __half* bLane;  __half* bIn[4]; __half* bXp[4]; __half* bDt[4]; __half* bOut[4];
    __half* bQ; __half* bK; __half* bV; __half* bO; __half* bLin;
    {
        int di = 0; size_t off = 0; int tiles = 0;
        auto add = [&](const float* W, int K, int N, __half** save) {
            da.W[di] = W; da.dst[di] = pB + off; da.K[di] = K; da.N[di] = N;
            da.tileBase[di] = tiles;
            *save = pB + off;
            off += (size_t)N * 3 * K;
            tiles += (K >> 5) * (N >> 5);
            di++;
        };
        add(lane_W, 128, DM_, &bLane);
        for (int i = 0; i < 4; i++) add(inpW + (size_t)i * DM_ * 2 * DI_, DM_, 2 * DI_, &bIn[i]);
        for (int i = 0; i < 4; i++) add(xprW + (size_t)i * DI_ * 64,      DI_, 64,      &bXp[i]);
        for (int i = 0; i < 4; i++) add(dtW  + (size_t)i * DTR_ * DI_,    DTR_, DI_,    &bDt[i]);
        for (int i = 0; i < 4; i++) add(outW + (size_t)i * DI_ * DM_,     DI_, DM_,     &bOut[i]);
        add(Wq,  DM_, DM_, &bQ);
        add(Wk,  DM_, DM_, &bK);
        add(Wv,  DM_, DM_, &bV);
        add(Wo,  DM_, DM_, &bO);
        add(linW, DM_, DM_, &bLin);
        da.bk = bk; da.bv = bv; da.bkv = pbkv;
        splitB_all<<<tiles, dim3(32, 8)>>>(da);
    }
    // activation splits for constant inputs
    splitA_kernel<<<(ROWS_K * 256 + 255) / 256, 256>>>(agent, DM_, 8, ROWS_K * 256, pAag);
    splitA_kernel<<<(ROWS_Q * 64 + 255) / 256, 256>>>(lane, 128, 6, ROWS_Q * 64, pA6);

    // lane_in (Keff=384)
    mma_gemm_pipe<64,128,false,false><<<dim3(DM_/128, ROWS_Q/64), 256, SMEM_PIPE_64M>>>(pA6, bLane, lane_b, px, DM_, 3*128);

    for (int i = 0; i < NBLK_; i++) {
        rmsnorm_split_kernel<<<ROWS_Q, 128>>>(px, norm_w + i * DM_, pA6);
        // in_proj: Keff=1536, N=2048
        mma_gemm_pipe<128,128,false,false><<<dim3(2*DI_/128, ROWS_Q/128), 256, SMEM_PIPE_128>>>(pA6, bIn[i], nullptr, pxz, 2*DI_, 3*DM_);
        conv_silu_split_kernel<<<(B_*LQ_*DI_/2 + 255) / 256, 256>>>(pxz,
            convw + (size_t)i * DI_ * 4, convb + (size_t)i * DI_, pxc, pA6);
        // x_proj: Keff=3072, N=64
        mma_gemm_pipe<64,64,false,false><<<dim3(1, ROWS_Q/64), 256, SMEM_PIPE_64S>>>(pA6, bXp[i], nullptr, pdbl, 64, 3*DI_);
        // dt_proj: fp32 A inline split, softplus
        dt_gemm<<<dim3(DI_/128, ROWS_Q/128), 256, SMEM_DT>>>(pdbl, bDt[i], dtb + (size_t)i * DI_, pdlt);
        // scan -> A6
        scan_kernel<<<128, 256>>>(pdlt, pxc, pdbl, pxz,
            A_log + (size_t)i * DI_ * DS_, Dskip + (size_t)i * DI_, pA6);
        // out_proj (+= residual)
        mma_gemm_pipe<64,128,true,false><<<dim3(DM_/128, ROWS_Q/64), 256, SMEM_PIPE_64M>>>(pA6, bOut[i], nullptr, px, DM_, 3*DI_);
    }

    rmsnorm_split_kernel<<<ROWS_Q, 128>>>(px, fnw, pA6);
    mma_gemm_pipe<64,128,false,false><<<dim3(DM_/128, ROWS_Q/64), 256, SMEM_PIPE_64M>>>(pA6, bQ, bq, pq, DM_, 3*DM_);

    // combined K|V projection: N=1024 (bK,bV contiguous in arena), bias pbkv
    mma_gemm_pipe<64,128,false,false><<<dim3(KVS_/128, ROWS_K/64), 256, SMEM_PIPE_64M>>>(pAag, bK, pbkv, pkv, KVS_, 3*DM_);

    attn_kernel<<<dim3(LQ_/16, NHEAD_, B_), 256>>>(pq, pkv, pA6);

    // Wo: split-out epilogue -> DISJOINT buffer pA6b (fixes R14 in-place race)
    mma_gemm_pipe<64,128,false,true><<<dim3(DM_/128, ROWS_Q/64), 256, SMEM_PIPE_64M>>>(pA6, bO, bo, (float*)pA6b, DM_, 3*DM_);
    // lin_in reads pA6b
    mma_gemm_pipe<64,128,false,false><<<dim3(DM_/128, ROWS_Q/64), 256, SMEM_PIPE_64M>>>(pA6b, bLin, linb, ph, DM_, 3*DM_);

    int writePreds = (out_size >= ROWS_Q * NOUT_ + ROWS_Q) ? 1 : 0;
    head_gemm_kernel<<<dim3(1, ROWS_Q/64), 256>>>(ph, loutW, loutb, probs,
        probs + ROWS_Q * NOUT_, writePreds, ROWS_Q, NOUT_, DM_);
}